// round 16
// baseline (speedup 1.0000x reference)
#include <cuda_runtime.h>
#include <cuda_fp16.h>
#include <stdint.h>

#define B_   2
#define S_   2048
#define D_   1024
#define MTOK 4096
#define BH_  32
#define BKP  40
#define CORRF (64.0f/65.0f)

typedef __half f16;

// ------------------------- scratch -------------------------
__device__ f16 g_tq[MTOK*D_];
__device__ f16 g_tk[MTOK*D_];
__device__ f16 g_tv[MTOK*D_];
__device__ f16 g_wq[D_*D_], g_wk[D_*D_], g_wv[D_*D_];
__device__ f16 g_wo_hi[D_*D_], g_wo_lo[D_*D_];      // Wo: B-side pair (O-proj 2-pass)
__device__ f16 g_q[MTOK*D_];                        // Q proj fp16, scaled 1/8
__device__ f16 g_k[MTOK*D_];
__device__ f16 g_vt[MTOK*D_];                       // V proj fp16, [bh][d][s]
__device__ f16 g_c_hi[MTOK*D_], g_c_lo[MTOK*D_];    // context: A-side pair

// ------------------------- helpers -------------------------
__device__ __forceinline__ uint32_t sptr(const void* p) {
    return (uint32_t)__cvta_generic_to_shared(p);
}
__device__ __forceinline__ void cp16(void* smem, const void* g) {
    asm volatile("cp.async.cg.shared.global [%0], [%1], 16;\n" :: "r"(sptr(smem)), "l"(g));
}
#define CP_COMMIT asm volatile("cp.async.commit_group;\n")

__device__ __forceinline__ void ldsm4(uint32_t* r, uint32_t a) {
    asm volatile("ldmatrix.sync.aligned.m8n8.x4.shared.b16 {%0,%1,%2,%3}, [%4];\n"
        : "=r"(r[0]), "=r"(r[1]), "=r"(r[2]), "=r"(r[3]) : "r"(a));
}
__device__ __forceinline__ void ldsm2(uint32_t* r, uint32_t a) {
    asm volatile("ldmatrix.sync.aligned.m8n8.x2.shared.b16 {%0,%1}, [%2];\n"
        : "=r"(r[0]), "=r"(r[1]) : "r"(a));
}

__device__ __forceinline__ void mma_f16(float c[4], const uint32_t a[4], const uint32_t b[2])
{
    asm volatile(
        "mma.sync.aligned.m16n8k16.row.col.f32.f16.f16.f32 "
        "{%0,%1,%2,%3}, {%4,%5,%6,%7}, {%8,%9}, {%0,%1,%2,%3};\n"
        : "+f"(c[0]), "+f"(c[1]), "+f"(c[2]), "+f"(c[3])
        : "r"(a[0]), "r"(a[1]), "r"(a[2]), "r"(a[3]), "r"(b[0]), "r"(b[1]));
}

// A-side pair: hi = fp16(v), m = fp16(hi + 64*(v - hi))
__device__ __forceinline__ void store_A(float v, f16* hi, f16* m, size_t i)
{
    __half h = __float2half(v);
    float hf = __half2float(h);
    hi[i] = h;
    m[i] = __float2half(hf + 64.0f*(v - hf));
}
// B-side pair: hi = fp16(v), m = fp16(hi/64 + (v - hi))
__device__ __forceinline__ void store_B(float v, f16* hi, f16* m, size_t i)
{
    __half h = __float2half(v);
    float hf = __half2float(h);
    hi[i] = h;
    m[i] = __float2half(hf*(1.0f/64.0f) + (v - hf));
}

// ------------------------- split (7 tensors, one launch) --------------------
struct SplitArgs {
    const float* src[7];
    f16* hi[7];
    f16* lo[7];
};
#define NT (MTOK*D_)
#define NW (D_*D_)

__global__ __launch_bounds__(256) void split_all_kernel(SplitArgs a)
{
    int bid = blockIdx.x;
    int z, base;
    if (bid < 3 * (NT/256)) { z = bid / (NT/256); base = (bid % (NT/256)) * 256; }
    else { int r = bid - 3*(NT/256); z = 3 + r / (NW/256); base = (r % (NW/256)) * 256; }
    int i = base + threadIdx.x;
    float v = a.src[z][i];
    if (z < 6) a.hi[z][i] = __float2half(v);
    else       store_B(v, a.hi[z], a.lo[z], i);
}

// ------------------------- 1-pass QKV projection GEMM -----------------------
#define P1_SMEM (4*128*BKP*2)

__device__ __forceinline__ void stage1(f16* d, const f16* S, int r0, int kt, int srow, int sch)
{
    cp16(d +  srow      * BKP + sch, S + (size_t)(r0 + srow)      * D_ + kt + sch);
    cp16(d + (srow + 64) * BKP + sch, S + (size_t)(r0 + srow + 64) * D_ + kt + sch);
}

__global__ __launch_bounds__(256) void proj_qkv_kernel(
    const f16* __restrict__ A0, const f16* __restrict__ W0, const float* __restrict__ b0,
    const f16* __restrict__ A1, const f16* __restrict__ W1, const float* __restrict__ b1,
    const f16* __restrict__ A2, const f16* __restrict__ W2, const float* __restrict__ b2,
    f16* __restrict__ O0, f16* __restrict__ O1, f16* __restrict__ O2)
{
    extern __shared__ f16 sm[];
    #define UA(buf) (sm + (buf) * (128*BKP))
    #define UB(buf) (sm + (2 + (buf)) * (128*BKP))
    const int z = blockIdx.z;
    const f16* A = z == 0 ? A0 : (z == 1 ? A1 : A2);
    const f16* W = z == 0 ? W0 : (z == 1 ? W1 : W2);
    const float* bias = z == 0 ? b0 : (z == 1 ? b1 : b2);
    f16* Oh = z == 0 ? O0 : (z == 1 ? O1 : O2);
    const float scale = z == 0 ? 0.125f : 1.0f;

    const int tid = threadIdx.x, lane = tid & 31, wid = tid >> 5;
    const int g = lane >> 2, t = lane & 3;
    const int wm = (wid >> 2) * 64, wn = (wid & 3) * 32;
    const int m0 = blockIdx.y * 128, n0 = blockIdx.x * 128;
    const int srow = tid >> 2, sch = (tid & 3) * 8;
    const uint32_t aoff = (uint32_t)((lane & 15) * BKP * 2 + (lane >> 4) * 16);
    const uint32_t boff = (uint32_t)((lane & 7) * BKP * 2 + ((lane >> 3) & 1) * 16);

    float acc[4][4][4] = {};
    stage1(UA(0), A, m0, 0, srow, sch);
    stage1(UB(0), W, n0, 0, srow, sch);
    CP_COMMIT;

    for (int kt = 0; kt < D_; kt += 32) {
        const int cur = (kt >> 5) & 1;
        asm volatile("cp.async.wait_group 0;\n");
        __syncthreads();
        if (kt + 32 < D_) {
            stage1(UA(cur^1), A, m0, kt + 32, srow, sch);
            stage1(UB(cur^1), W, n0, kt + 32, srow, sch);
            CP_COMMIT;
        }
        const uint32_t ab = sptr(UA(cur)), bb = sptr(UB(cur));
        #pragma unroll
        for (int kk = 0; kk < 32; kk += 16) {
            uint32_t aH[4][4], bH[4][2];
            #pragma unroll
            for (int mt = 0; mt < 4; ++mt)
                ldsm4(aH[mt], ab + (uint32_t)(((wm + mt*16)*BKP + kk) * 2) + aoff);
            #pragma unroll
            for (int nt = 0; nt < 4; ++nt)
                ldsm2(bH[nt], bb + (uint32_t)(((wn + nt*8)*BKP + kk) * 2) + boff);
            #pragma unroll
            for (int mt = 0; mt < 4; ++mt)
                #pragma unroll
                for (int nt = 0; nt < 4; ++nt)
                    mma_f16(acc[mt][nt], aH[mt], bH[nt]);
        }
        __syncthreads();
    }

    #pragma unroll
    for (int mt = 0; mt < 4; ++mt) {
        int row0 = m0 + wm + mt*16 + g;
        #pragma unroll
        for (int nt = 0; nt < 4; ++nt) {
            int col = n0 + wn + nt*8 + 2*t;
            float v[4];
            v[0] = (acc[mt][nt][0] + bias[col])   * scale;
            v[1] = (acc[mt][nt][1] + bias[col+1]) * scale;
            v[2] = (acc[mt][nt][2] + bias[col])   * scale;
            v[3] = (acc[mt][nt][3] + bias[col+1]) * scale;
            if (z != 2) {
                size_t i0 = (size_t)row0 * D_ + col, i1 = (size_t)(row0+8) * D_ + col;
                __half2 a01 = __floats2half2_rn(v[0], v[1]);
                __half2 a23 = __floats2half2_rn(v[2], v[3]);
                *(uint32_t*)(Oh + i0) = *(uint32_t*)&a01;
                *(uint32_t*)(Oh + i1) = *(uint32_t*)&a23;
            } else {  // V transposed: [bh][d][s]
                #pragma unroll
                for (int e = 0; e < 4; ++e) {
                    int row = row0 + (e >> 1) * 8, c = col + (e & 1);
                    size_t i = (((size_t)(row >> 11) * 16 + (c >> 6)) * 64 + (c & 63)) * S_
                             + (row & (S_-1));
                    Oh[i] = __float2half(v[e]);
                }
            }
        }
    }
    #undef UA
    #undef UB
}

// ------------------------- 2-pass O projection ------------------------------
#define GEMM_SMEM (8*128*BKP*2)

__device__ __forceinline__ void stage128(f16* dh, f16* dl,
    const f16* Sh, const f16* Sl, int r0, int kt, int srow, int sch)
{
    size_t a0 = (size_t)(r0 + srow)      * D_ + kt + sch;
    size_t a1 = (size_t)(r0 + srow + 64) * D_ + kt + sch;
    cp16(dh +  srow      * BKP + sch, Sh + a0);
    cp16(dh + (srow + 64) * BKP + sch, Sh + a1);
    cp16(dl +  srow      * BKP + sch, Sl + a0);
    cp16(dl + (srow + 64) * BKP + sch, Sl + a1);
}

__global__ __launch_bounds__(256) void proj_o_kernel(
    const f16* __restrict__ Ahi, const f16* __restrict__ Alo,
    const f16* __restrict__ Whi, const f16* __restrict__ Wlo,
    const float* __restrict__ bias, float* __restrict__ Of)
{
    extern __shared__ f16 sm[];
    #define TA(buf,hl) (sm + ((buf)*2 + (hl)) * (128*BKP))
    #define TB(buf,hl) (sm + (4 + (buf)*2 + (hl)) * (128*BKP))
    const int tid = threadIdx.x, lane = tid & 31, wid = tid >> 5;
    const int g = lane >> 2, t = lane & 3;
    const int wm = (wid >> 2) * 64, wn = (wid & 3) * 32;
    const int m0 = blockIdx.y * 128, n0 = blockIdx.x * 128;
    const int srow = tid >> 2, sch = (tid & 3) * 8;
    const uint32_t aoff = (uint32_t)((lane & 15) * BKP * 2 + (lane >> 4) * 16);
    const uint32_t boff = (uint32_t)((lane & 7) * BKP * 2 + ((lane >> 3) & 1) * 16);

    float acc[4][4][4] = {};
    stage128(TA(0,0), TA(0,1), Ahi, Alo, m0, 0, srow, sch);
    stage128(TB(0,0), TB(0,1), Whi, Wlo, n0, 0, srow, sch);
    CP_COMMIT;

    for (int kt = 0; kt < D_; kt += 32) {
        const int cur = (kt >> 5) & 1;
        asm volatile("cp.async.wait_group 0;\n");
        __syncthreads();
        if (kt + 32 < D_) {
            stage128(TA(cur^1,0), TA(cur^1,1), Ahi, Alo, m0, kt + 32, srow, sch);
            stage128(TB(cur^1,0), TB(cur^1,1), Whi, Wlo, n0, kt + 32, srow, sch);
            CP_COMMIT;
        }
        const uint32_t ah = sptr(TA(cur,0)), am = sptr(TA(cur,1));
        const uint32_t bh = sptr(TB(cur,0)), bm = sptr(TB(cur,1));
        #pragma unroll
        for (int kk = 0; kk < 32; kk += 16) {
            uint32_t aH[4][4], aM[4][4], bH[4][2], bM[4][2];
            #pragma unroll
            for (int mt = 0; mt < 4; ++mt) {
                uint32_t base = (uint32_t)(((wm + mt*16)*BKP + kk) * 2);
                ldsm4(aH[mt], ah + base + aoff);
                ldsm4(aM[mt], am + base + aoff);
            }
            #pragma unroll
            for (int nt = 0; nt < 4; ++nt) {
                uint32_t base = (uint32_t)(((wn + nt*8)*BKP + kk) * 2);
                ldsm2(bH[nt], bh + base + boff);
                ldsm2(bM[nt], bm + base + boff);
            }
            #pragma unroll
            for (int mt = 0; mt < 4; ++mt)
                #pragma unroll
                for (int nt = 0; nt < 4; ++nt) {
                    mma_f16(acc[mt][nt], aH[mt], bH[nt]);
                    mma_f16(acc[mt][nt], aM[mt], bM[nt]);
                }
        }
        __syncthreads();
    }

    #pragma unroll
    for (int mt = 0; mt < 4; ++mt) {
        int row0 = m0 + wm + mt*16 + g;
        #pragma unroll
        for (int nt = 0; nt < 4; ++nt) {
            int col = n0 + wn + nt*8 + 2*t;
            size_t i0 = (size_t)row0 * D_ + col, i1 = (size_t)(row0+8) * D_ + col;
            Of[i0]   = acc[mt][nt][0]*CORRF + bias[col];
            Of[i0+1] = acc[mt][nt][1]*CORRF + bias[col+1];
            Of[i1]   = acc[mt][nt][2]*CORRF + bias[col];
            Of[i1+1] = acc[mt][nt][3]*CORRF + bias[col+1];
        }
    }
    #undef TA
    #undef TB
}

// ------------------------- flash attention (128-q tile, 8 m-warps) ----------
// smem: Qs 18432 | Ks 2x9216 | Vs 2x9216 | Ms 8192 = 63488 bytes
#define KCH  64
#define KPL  (64*72)
#define FLASH_SMEM 63488

__global__ __launch_bounds__(256, 2) void flash_kernel(const int* __restrict__ mask)
{
    extern __shared__ char smc[];
    f16* Qs = (f16*)smc;                   // [128][72]
    f16* Ks = (f16*)(smc + 18432);         // [buf][64][72]
    f16* Vs = (f16*)(smc + 36864);         // [buf][64][72]
    int* Ms = (int*)(smc + 55296);         // [2048]

    const int bh = blockIdx.y, b = bh >> 4, h = bh & 15;
    const int q0 = blockIdx.x * 128;
    const int tid = threadIdx.x, lane = tid & 31, wid = tid >> 5;
    const int g = lane >> 2, t = lane & 3;
    const int mg = wid;                 // each warp owns 16 q rows

    const int kr = tid >> 2, kc = (tid & 3) * 16;   // K/V staging: 64 rows x 64
    const int qr = tid >> 1, qc = (tid & 1) * 32;   // Q staging: 128 rows x 64

    const uint32_t aoff72 = (uint32_t)((lane & 15) * 144 + (lane >> 4) * 16);
    const uint32_t boff72 = (uint32_t)((lane & 7) * 144 + ((lane >> 3) & 1) * 16);
    const uint32_t qs_base = sptr(Qs);

    {
        size_t gq = ((size_t)(b*S_ + q0 + qr))*D_ + h*64 + qc;
        cp16(Qs + qr*72 + qc,      g_q + gq);
        cp16(Qs + qr*72 + qc + 8,  g_q + gq + 8);
        cp16(Qs + qr*72 + qc + 16, g_q + gq + 16);
        cp16(Qs + qr*72 + qc + 24, g_q + gq + 24);
        size_t gk = ((size_t)(b*S_ + kr))*D_ + h*64 + kc;
        cp16(Ks + kr*72 + kc,     g_k + gk);
        cp16(Ks + kr*72 + kc + 8, g_k + gk + 8);
        size_t gv = ((size_t)(bh*64 + kr))*S_ + kc;
        cp16(Vs + kr*72 + kc,     g_vt + gv);
        cp16(Vs + kr*72 + kc + 8, g_vt + gv + 8);
        cp16(Ms + tid*8,     mask + b*S_ + tid*8);
        cp16(Ms + tid*8 + 4, mask + b*S_ + tid*8 + 4);
        CP_COMMIT;
    }

    float acc_o[8][4] = {};
    float ls[2] = {};

    for (int it = 0; it < 32; ++it) {
        const int cur = it & 1;
        if (it < 31) {
            size_t gk = ((size_t)(b*S_ + (it+1)*KCH + kr))*D_ + h*64 + kc;
            f16* dk = Ks + (cur^1)*KPL + kr*72 + kc;
            cp16(dk,     g_k + gk);
            cp16(dk + 8, g_k + gk + 8);
            size_t gv = ((size_t)(bh*64 + kr))*S_ + (it+1)*KCH + kc;
            f16* dv = Vs + (cur^1)*KPL + kr*72 + kc;
            cp16(dv,     g_vt + gv);
            cp16(dv + 8, g_vt + gv + 8);
            CP_COMMIT;
            asm volatile("cp.async.wait_group 1;\n");
        } else {
            asm volatile("cp.async.wait_group 0;\n");
        }
        __syncthreads();

        // ---- scores: Q[16q x 64dk] . K_chunk[64k x 64dk]^T ----
        float accs[8][4] = {};
        const uint32_t kb = sptr(Ks + cur*KPL);
        #pragma unroll
        for (int kk = 0; kk < 64; kk += 16) {
            uint32_t aH[4], bHf[8][2];
            uint32_t abase = (uint32_t)(((mg*16)*72 + kk) * 2);
            ldsm4(aH, qs_base + abase + aoff72);
            #pragma unroll
            for (int nt = 0; nt < 8; ++nt) {
                uint32_t base = (uint32_t)(((nt*8)*72 + kk) * 2);
                ldsm2(bHf[nt], kb + base + boff72);
            }
            #pragma unroll
            for (int nt = 0; nt < 8; ++nt)
                mma_f16(accs[nt], aH, bHf[nt]);
        }

        // ---- mask + exp + pack P ----
        uint32_t pP[4][4];
        #pragma unroll
        for (int nt = 0; nt < 8; ++nt) {
            int c0 = it*KCH + nt*8 + 2*t;
            bool m0 = Ms[c0] != 0, m1 = Ms[c0+1] != 0;
            float p0 = m0 ? __expf(accs[nt][0]) : 0.f;
            float p1 = m1 ? __expf(accs[nt][1]) : 0.f;
            float p2 = m0 ? __expf(accs[nt][2]) : 0.f;
            float p3 = m1 ? __expf(accs[nt][3]) : 0.f;
            ls[0] += p0 + p1;
            ls[1] += p2 + p3;
            int jj = nt >> 1, hf = (nt & 1) * 2;
            __half2 h01 = __floats2half2_rn(p0, p1);
            __half2 h23 = __floats2half2_rn(p2, p3);
            pP[jj][hf]   = *(uint32_t*)&h01;
            pP[jj][hf+1] = *(uint32_t*)&h23;
        }

        // ---- P[16q x 64k] . V_chunk[64k x 64d] ----
        const uint32_t vb = sptr(Vs + cur*KPL);
        #pragma unroll
        for (int jj = 0; jj < 4; ++jj) {
            uint32_t bHf[8][2];
            #pragma unroll
            for (int dt = 0; dt < 8; ++dt) {
                uint32_t base = (uint32_t)(((dt*8)*72 + jj*16) * 2);
                ldsm2(bHf[dt], vb + base + boff72);
            }
            #pragma unroll
            for (int dt = 0; dt < 8; ++dt)
                mma_f16(acc_o[dt], pP[jj], bHf[dt]);
        }
        __syncthreads();
    }

    // ---- in-warp l reduce + direct register->gmem ctx store ----
    float s0 = ls[0], s1 = ls[1];
    s0 += __shfl_xor_sync(~0u, s0, 1);  s0 += __shfl_xor_sync(~0u, s0, 2);
    s1 += __shfl_xor_sync(~0u, s1, 1);  s1 += __shfl_xor_sync(~0u, s1, 2);
    float inv0 = 1.0f / s0, inv1 = 1.0f / s1;

    const int r0 = q0 + mg*16 + g;
    #pragma unroll
    for (int dt = 0; dt < 8; ++dt) {
        int d = dt*8 + 2*t;
        size_t o0 = ((size_t)(b*S_ + r0))     * D_ + h*64 + d;
        size_t o1 = ((size_t)(b*S_ + r0 + 8)) * D_ + h*64 + d;
        store_A(acc_o[dt][0]*inv0, g_c_hi, g_c_lo, o0);
        store_A(acc_o[dt][1]*inv0, g_c_hi, g_c_lo, o0 + 1);
        store_A(acc_o[dt][2]*inv1, g_c_hi, g_c_lo, o1);
        store_A(acc_o[dt][3]*inv1, g_c_hi, g_c_lo, o1 + 1);
    }
}

// ------------------------- launch -------------------------
extern "C" void kernel_launch(void* const* d_in, const int* in_sizes, int n_in,
                              void* d_out, int out_size)
{
    const float* query = (const float*)d_in[0];
    const float* key   = (const float*)d_in[1];
    const float* value = (const float*)d_in[2];
    const int*   mask  = (const int*)d_in[3];
    const float* Wq = (const float*)d_in[4];  const float* bq = (const float*)d_in[5];
    const float* Wk = (const float*)d_in[6];  const float* bk = (const float*)d_in[7];
    const float* Wv = (const float*)d_in[8];  const float* bv = (const float*)d_in[9];
    const float* Wo = (const float*)d_in[10]; const float* bo = (const float*)d_in[11];
    float* out = (float*)d_out;

    cudaFuncSetAttribute(proj_qkv_kernel, cudaFuncAttributeMaxDynamicSharedMemorySize, P1_SMEM);
    cudaFuncSetAttribute(proj_o_kernel,   cudaFuncAttributeMaxDynamicSharedMemorySize, GEMM_SMEM);
    cudaFuncSetAttribute(flash_kernel,    cudaFuncAttributeMaxDynamicSharedMemorySize, FLASH_SMEM);

    f16 *tq,*tk,*tv,*wq,*wk,*wv,*woh,*wol,*qp,*kp,*vtp,*ch,*cl;
    cudaGetSymbolAddress((void**)&tq,  g_tq);
    cudaGetSymbolAddress((void**)&tk,  g_tk);
    cudaGetSymbolAddress((void**)&tv,  g_tv);
    cudaGetSymbolAddress((void**)&wq,  g_wq);
    cudaGetSymbolAddress((void**)&wk,  g_wk);
    cudaGetSymbolAddress((void**)&wv,  g_wv);
    cudaGetSymbolAddress((void**)&woh, g_wo_hi);
    cudaGetSymbolAddress((void**)&wol, g_wo_lo);
    cudaGetSymbolAddress((void**)&qp,  g_q);
    cudaGetSymbolAddress((void**)&kp,  g_k);
    cudaGetSymbolAddress((void**)&vtp, g_vt);
    cudaGetSymbolAddress((void**)&ch,  g_c_hi);
    cudaGetSymbolAddress((void**)&cl,  g_c_lo);

    SplitArgs sa;
    sa.src[0] = query; sa.hi[0] = tq;  sa.lo[0] = nullptr;
    sa.src[1] = key;   sa.hi[1] = tk;  sa.lo[1] = nullptr;
    sa.src[2] = value; sa.hi[2] = tv;  sa.lo[2] = nullptr;
    sa.src[3] = Wq;    sa.hi[3] = wq;  sa.lo[3] = nullptr;
    sa.src[4] = Wk;    sa.hi[4] = wk;  sa.lo[4] = nullptr;
    sa.src[5] = Wv;    sa.hi[5] = wv;  sa.lo[5] = nullptr;
    sa.src[6] = Wo;    sa.hi[6] = woh; sa.lo[6] = wol;
    split_all_kernel<<<3*(NT/256) + 4*(NW/256), 256>>>(sa);

    proj_qkv_kernel<<<dim3(D_/128, MTOK/128, 3), 256, P1_SMEM>>>(
        tq, wq, bq, tk, wk, bk, tv, wv, bv, qp, kp, vtp);

    flash_kernel<<<dim3(S_/128, BH_), 256, FLASH_SMEM>>>(mask);

    proj_o_kernel<<<dim3(D_/128, MTOK/128), 256, GEMM_SMEM>>>(ch, cl, woh, wol, bo, out);
}